// round 16
// baseline (speedup 1.0000x reference)
#include <cuda_runtime.h>
#include <cuda_fp16.h>
#include <math.h>
#include <stdint.h>

#define B_     16
#define T_     2048
#define C_     512
#define G_     2
#define D_     256
#define V_     320
#define N_TOK  (B_*T_)           // 32768
#define NPAIR  (N_TOK*G_)        // 65536
#define GN_N   ((double)(T_*D_)) // 524288
#define THRESH 2.5e-4f
#define SCAL   256.0f
#define INVS   (1.0f/256.0f)

typedef unsigned long long ull;

// ---------------- scratch ----------------------------------------------------
__device__ float      g_y  [N_TOK*C_];
__device__ float      g_zsq[NPAIR];
__device__ ulonglong2 g_top2[NPAIR*8];   // [pair][nh 0..7]
__device__ int        g_idx[NPAIR];
__device__ int        g_wl [NPAIR];
__device__ int        g_wlc;
__device__ double     g_p1s[32][64];
__device__ double     g_p1q[32][64];
__device__ float      g_mu  [32];
__device__ float      g_rstd[32];
__device__ float      g_esq [G_*V_];
__device__ int        g_hist[G_*V_];
__device__ double     g_lpart[8192];

// fragment-packed operands (half2 planes, hi and lo)
__device__ uint32_t g_xh[2*256*16384];
__device__ uint32_t g_xl[2*256*16384];
__device__ uint32_t g_zh[2*256*16384];
__device__ uint32_t g_zl[2*256*16384];
__device__ uint32_t g_wh[2*32768];       // w   [g][kc][nt(32)][lane][reg]
__device__ uint32_t g_wl_[2*32768];
__device__ uint32_t g_eh[2*40960];       // emb [g][kc][nt(40)][lane][reg]
__device__ uint32_t g_el[2*40960];

// ---------------- helpers ----------------------------------------------------
__device__ __forceinline__ void mma_f16(float4& c, const uint4& a, const uint2& b){
    asm("mma.sync.aligned.m16n8k16.row.col.f32.f16.f16.f32 "
        "{%0,%1,%2,%3}, {%4,%5,%6,%7}, {%8,%9}, {%0,%1,%2,%3};"
        : "+f"(c.x), "+f"(c.y), "+f"(c.z), "+f"(c.w)
        : "r"(a.x), "r"(a.y), "r"(a.z), "r"(a.w), "r"(b.x), "r"(b.y));
}
__device__ __forceinline__ uint32_t hsplit(float v0, float v1, uint32_t& lo){
    __half h0 = __float2half_rn(v0), h1 = __float2half_rn(v1);
    __half l0 = __float2half_rn(v0 - __half2float(h0));
    __half l1 = __float2half_rn(v1 - __half2float(h1));
    __half2 H = __halves2half2(h0, h1), L = __halves2half2(l0, l1);
    lo = *reinterpret_cast<uint32_t*>(&L);
    return *reinterpret_cast<uint32_t*>(&H);
}
__device__ __forceinline__ void sts_A16(uint32_t* hi, uint32_t* lo,
                                        int row, int k, float v0, float v1){
    int kp = k >> 1, mt = row >> 4, r = row & 15;
    int reg = ((r >> 3) & 1) | (((kp >> 2) & 1) << 1);
    int idx = mt*128 + ((r & 7)*4 + (kp & 3))*4 + reg;
    uint32_t L, H = hsplit(v0, v1, L);
    hi[idx] = H; lo[idx] = L;
}
template<int NT>
__device__ __forceinline__ void sts_B16(uint32_t* hi, uint32_t* lo,
                                        int n, int k, float v0, float v1){
    int kp = k >> 1, nt = n >> 3;
    int reg = (kp >> 2) & 1;
    int idx = nt*64 + ((n & 7)*4 + (kp & 3))*2 + reg;
    uint32_t L, H = hsplit(v0, v1, L);
    hi[idx] = H; lo[idx] = L;
}
__device__ __forceinline__ void ld8(const float* __restrict__ p, float* r){
    float4 a = *(const float4*)p;
    float4 b = *(const float4*)(p + 4);
    r[0]=a.x; r[1]=a.y; r[2]=a.z; r[3]=a.w;
    r[4]=b.x; r[5]=b.y; r[6]=b.z; r[7]=b.w;
}
__device__ __forceinline__ ull umin2(ull a, ull b){ return a < b ? a : b; }
__device__ __forceinline__ ull umax2(ull a, ull b){ return a > b ? a : b; }
__device__ __forceinline__ void upd2(ull& b1, ull& b2, ull p){
    if (p < b1){ b2 = b1; b1 = p; }
    else if (p < b2){ b2 = p; }
}
__device__ __forceinline__ void cp16(uint32_t d, const void* s){
    asm volatile("cp.async.ca.shared.global [%0], [%1], 16;" :: "r"(d), "l"(s));
}
#define CP_COMMIT() asm volatile("cp.async.commit_group;" ::: "memory")
#define CP_WAIT0()  asm volatile("cp.async.wait_group 0;"  ::: "memory")

__global__ void k_nop(){}

// ---------------- K0: setup (pack w, pack emb, init) -------------------------
__global__ __launch_bounds__(256) void k_setup(const float* __restrict__ w,
                                               const float* __restrict__ emb){
    __shared__ uint32_t sh[2560], sl[2560];
    int bid = blockIdx.x, tid = threadIdx.x;
    if (bid < 32){
        int g = bid >> 4, kc = bid & 15;
        const float* Bg = w + (size_t)g*D_*D_;
        #pragma unroll
        for (int it = 0; it < 4; it++){
            int f4 = it*256 + tid, row = f4 >> 2, kq = (f4 & 3)*4;
            float4 v = *(const float4*)(Bg + (size_t)row*D_ + kc*16 + kq);
            sts_B16<32>(sh, sl, row, kq,   v.x*SCAL, v.y*SCAL);
            sts_B16<32>(sh, sl, row, kq+2, v.z*SCAL, v.w*SCAL);
        }
        __syncthreads();
        #pragma unroll
        for (int j = 0; j < 8; j++){
            g_wh [g*32768 + kc*2048 + j*256 + tid] = sh[j*256 + tid];
            g_wl_[g*32768 + kc*2048 + j*256 + tid] = sl[j*256 + tid];
        }
    } else if (bid < 64){
        int g = (bid-32) >> 4, kc = (bid-32) & 15;
        const float* Bg = emb + g*D_;
        #pragma unroll
        for (int it = 0; it < 5; it++){
            int f4 = it*256 + tid, row = f4 >> 2, kq = (f4 & 3)*4;
            float4 v = *(const float4*)(Bg + (size_t)row*C_ + kc*16 + kq);
            sts_B16<40>(sh, sl, row, kq,   v.x*SCAL, v.y*SCAL);
            sts_B16<40>(sh, sl, row, kq+2, v.z*SCAL, v.w*SCAL);
        }
        __syncthreads();
        #pragma unroll
        for (int j = 0; j < 10; j++){
            g_eh[g*40960 + kc*2560 + j*256 + tid] = sh[j*256 + tid];
            g_el[g*40960 + kc*2560 + j*256 + tid] = sl[j*256 + tid];
        }
    } else {
        int i = (bid - 64)*256 + tid;
        if (i == 0) g_wlc = 0;
        if (i < G_*V_){
            g_hist[i] = 0;
            int g = i / V_, v = i % V_;
            const float4* p = (const float4*)(emb + (size_t)v*C_ + g*D_);
            float s = 0.f;
            #pragma unroll 16
            for (int q = 0; q < D_/4; q++){
                float4 e = p[q];
                s += e.x*e.x + e.y*e.y + e.z*e.z + e.w*e.w;
            }
            g_esq[i] = s;
        }
    }
}

// ---------------- K0b: pack x into fragment layout ---------------------------
__global__ __launch_bounds__(256) void k_pack_x(const float* __restrict__ x){
    __shared__ uint32_t sh[1024], sl[1024];
    int tile = blockIdx.x, g = blockIdx.y, tid = threadIdx.x;
    const float* Ag = x + (size_t)tile*128*C_ + g*D_;
    size_t base = ((size_t)(g*256 + tile)) * 16384;
    for (int kc = 0; kc < 16; kc++){
        #pragma unroll
        for (int it = 0; it < 2; it++){
            int f4 = it*256 + tid, row = f4 >> 2, kq = (f4 & 3)*4;
            float4 v = *(const float4*)(Ag + (size_t)row*C_ + kc*16 + kq);
            sts_A16(sh, sl, row, kq,   v.x, v.y);
            sts_A16(sh, sl, row, kq+2, v.z, v.w);
        }
        __syncthreads();
        #pragma unroll
        for (int j = 0; j < 4; j++){
            g_xh[base + kc*1024 + j*256 + tid] = sh[j*256 + tid];
            g_xl[base + kc*1024 + j*256 + tid] = sl[j*256 + tid];
        }
        __syncthreads();
    }
}

// ---------------- K1: GEMM1 — 16-row warps, N=64/CTA, 3 CTAs/SM --------------
// grid (256, 4, 2) = (tile, bn, g). warp w: rows 16w..16w+15, all 64 cols.
__global__ __launch_bounds__(256, 3) void k_gemm1(){
    __shared__ uint32_t sB[2][1024];     // [stage][hi 512 | lo 512]
    __shared__ double rs[256], rq[256];
    const int tile = blockIdx.x, bn = blockIdx.y, g = blockIdx.z;
    const int tid  = threadIdx.x;
    const int lane = tid & 31, wrp = tid >> 5;

    const uint32_t* Ah = g_xh + ((size_t)(g*256 + tile))*16384;
    const uint32_t* Al = g_xl + ((size_t)(g*256 + tile))*16384;
    const uint32_t* Bh = g_wh  + g*32768 + bn*512;
    const uint32_t* Bl = g_wl_ + g*32768 + bn*512;

    float4 c[8];
    #pragma unroll
    for (int j = 0; j < 8; j++) c[j] = make_float4(0.f,0.f,0.f,0.f);

    // staging: tid<128 copy hi (512 u32 = 128x16B), else lo
    const int pl = tid >> 7, t7 = tid & 127;
    const uint32_t* Bsrc = pl ? Bl : Bh;
    cp16((uint32_t)__cvta_generic_to_shared(&sB[0][pl*512 + t7*4]), Bsrc + t7*4);
    CP_COMMIT();

    const int aoff = wrp*128 + lane*4;
    uint4 nah = *(const uint4*)(Ah + aoff);
    uint4 nal = *(const uint4*)(Al + aoff);

    for (int kc = 0; kc < 16; kc++){
        CP_WAIT0();
        __syncthreads();
        if (kc < 15){
            cp16((uint32_t)__cvta_generic_to_shared(&sB[(kc+1)&1][pl*512 + t7*4]),
                 Bsrc + (kc+1)*2048 + t7*4);
            CP_COMMIT();
        }
        uint4 ah = nah, al = nal;
        if (kc < 15){
            int ao = (kc+1)*1024 + aoff;
            nah = *(const uint4*)(Ah + ao);
            nal = *(const uint4*)(Al + ao);
        }
        const uint32_t* sb = sB[kc & 1];
        int nb = lane*2;
        #pragma unroll
        for (int nt = 0; nt < 8; nt++){
            uint2 bh = *(const uint2*)(sb + nb + nt*64);
            uint2 bl = *(const uint2*)(sb + 512 + nb + nt*64);
            mma_f16(c[nt], ah, bh);
            mma_f16(c[nt], ah, bl);
            mma_f16(c[nt], al, bh);
        }
    }

    // epilogue: y = c/256 + deterministic block stats
    const int qr = lane >> 2, qc = (lane & 3)*2;
    double s = 0.0, q = 0.0;
    const int r0  = tile*128 + wrp*16 + qr;
    const int colbase = g*D_ + bn*64;
    #pragma unroll
    for (int nt = 0; nt < 8; nt++){
        float4 v = make_float4(c[nt].x*INVS, c[nt].y*INVS,
                               c[nt].z*INVS, c[nt].w*INVS);
        int col = colbase + nt*8 + qc;
        *(float2*)(g_y + (size_t)r0*C_ + col)     = make_float2(v.x, v.y);
        *(float2*)(g_y + (size_t)(r0+8)*C_ + col) = make_float2(v.z, v.w);
        s += (double)v.x + (double)v.y + (double)v.z + (double)v.w;
        q += (double)v.x*v.x + (double)v.y*v.y + (double)v.z*v.z + (double)v.w*v.w;
    }
    rs[tid] = s; rq[tid] = q;
    __syncthreads();
    for (int off = 128; off > 0; off >>= 1){
        if (tid < off){ rs[tid] += rs[tid+off]; rq[tid] += rq[tid+off]; }
        __syncthreads();
    }
    if (tid == 0){
        int b2g = (tile >> 4)*2 + g;
        g_p1s[b2g][(tile & 15)*4 + bn] = rs[0];
        g_p1q[b2g][(tile & 15)*4 + bn] = rq[0];
    }
}

// ---------------- K2: finalize groupnorm stats -------------------------------
__global__ void k_stats(){
    int i = threadIdx.x;
    if (i >= 32) return;
    double s = 0.0, q = 0.0;
    for (int j = 0; j < 64; j++){ s += g_p1s[i][j]; q += g_p1q[i][j]; }
    double mu  = s / GN_N;
    double var = q / GN_N - mu*mu;
    g_mu[i]   = (float)mu;
    g_rstd[i] = (float)(1.0 / sqrt(var + 1e-5));
}

// ---------------- K3: normalize -> ze frag pack + zsq ------------------------
__global__ __launch_bounds__(256) void k_norm(const float* __restrict__ gn_w,
                                              const float* __restrict__ gn_b){
    __shared__ uint32_t sh[1024], sl[1024];
    int tile = blockIdx.x, g = blockIdx.y, tid = threadIdx.x;
    int b = tile >> 4;
    float mu = g_mu[b*2 + g], rstd = g_rstd[b*2 + g];
    const float* Yg = g_y + (size_t)tile*128*C_ + g*D_;
    size_t base = ((size_t)(g*256 + tile)) * 16384;

    float zp0 = 0.f, zp1 = 0.f;
    for (int kc = 0; kc < 16; kc++){
        #pragma unroll
        for (int it = 0; it < 2; it++){
            int f4 = it*256 + tid, row = f4 >> 2, kq = (f4 & 3)*4;
            float4 y4 = *(const float4*)(Yg + (size_t)row*C_ + kc*16 + kq);
            float4 wv = *(const float4*)(gn_w + g*D_ + kc*16 + kq);
            float4 bv = *(const float4*)(gn_b + g*D_ + kc*16 + kq);
            float4 z;
            z.x = fmaf((y4.x - mu)*rstd, wv.x, bv.x);
            z.y = fmaf((y4.y - mu)*rstd, wv.y, bv.y);
            z.z = fmaf((y4.z - mu)*rstd, wv.z, bv.z);
            z.w = fmaf((y4.w - mu)*rstd, wv.w, bv.w);
            float p = (it == 0) ? zp0 : zp1;
            p = fmaf(z.x, z.x, p); p = fmaf(z.y, z.y, p);
            p = fmaf(z.z, z.z, p); p = fmaf(z.w, z.w, p);
            if (it == 0) zp0 = p; else zp1 = p;
            sts_A16(sh, sl, row, kq,   z.x, z.y);
            sts_A16(sh, sl, row, kq+2, z.z, z.w);
        }
        __syncthreads();
        #pragma unroll
        for (int j = 0; j < 4; j++){
            g_zh[base + kc*1024 + j*256 + tid] = sh[j*256 + tid];
            g_zl[base + kc*1024 + j*256 + tid] = sl[j*256 + tid];
        }
        __syncthreads();
    }
    float t0 = zp0, t1 = zp1;
    t0 += __shfl_xor_sync(0xffffffffu, t0, 1);
    t0 += __shfl_xor_sync(0xffffffffu, t0, 2);
    t1 += __shfl_xor_sync(0xffffffffu, t1, 1);
    t1 += __shfl_xor_sync(0xffffffffu, t1, 2);
    if ((tid & 3) == 0){
        int r0 = tid >> 2;
        g_zsq[(size_t)(tile*128 + r0)*2 + g]      = t0;
        g_zsq[(size_t)(tile*128 + 64 + r0)*2 + g] = t1;
    }
}

// ---------------- K4: VQ — 16-row warps, 40 cols/CTA, 4 CTAs/SM --------------
// grid (256, 8, 2) = (tile, nh, g). warp w: rows 16w..16w+15, 40 cols (5 nt).
__global__ __launch_bounds__(256, 4) void k_vq(){
    __shared__ uint32_t sV[2][640];      // [stage][hi 320 | lo 320]
    const int tile = blockIdx.x, nh = blockIdx.y, g = blockIdx.z;
    const int tid  = threadIdx.x;
    const int lane = tid & 31, wrp = tid >> 5;

    const uint32_t* Ah = g_zh + ((size_t)(g*256 + tile))*16384;
    const uint32_t* Al = g_zl + ((size_t)(g*256 + tile))*16384;
    const uint32_t* Bh = g_eh + g*40960 + nh*320;
    const uint32_t* Bl = g_el + g*40960 + nh*320;

    float4 c[5];
    #pragma unroll
    for (int j = 0; j < 5; j++) c[j] = make_float4(0.f,0.f,0.f,0.f);

    // staging: tid<80 hi (80x16B = 320 u32), tid in [80,160) lo
    const int loj = tid - 80;
    if (tid < 80)
        cp16((uint32_t)__cvta_generic_to_shared(&sV[0][tid*4]), Bh + tid*4);
    if (loj >= 0 && loj < 80)
        cp16((uint32_t)__cvta_generic_to_shared(&sV[0][320 + loj*4]), Bl + loj*4);
    CP_COMMIT();

    const int aoff = wrp*128 + lane*4;
    uint4 nah = *(const uint4*)(Ah + aoff);
    uint4 nal = *(const uint4*)(Al + aoff);

    for (int kc = 0; kc < 16; kc++){
        CP_WAIT0();
        __syncthreads();
        if (kc < 15){
            if (tid < 80)
                cp16((uint32_t)__cvta_generic_to_shared(&sV[(kc+1)&1][tid*4]),
                     Bh + (kc+1)*2560 + tid*4);
            if (loj >= 0 && loj < 80)
                cp16((uint32_t)__cvta_generic_to_shared(&sV[(kc+1)&1][320 + loj*4]),
                     Bl + (kc+1)*2560 + loj*4);
            CP_COMMIT();
        }
        uint4 ah = nah, al = nal;
        if (kc < 15){
            int ao = (kc+1)*1024 + aoff;
            nah = *(const uint4*)(Ah + ao);
            nal = *(const uint4*)(Al + ao);
        }
        const uint32_t* sb = sV[kc & 1];
        int nb = lane*2;
        #pragma unroll
        for (int nt = 0; nt < 5; nt++){
            uint2 bh = *(const uint2*)(sb + nb + nt*64);
            uint2 bl = *(const uint2*)(sb + 320 + nb + nt*64);
            mma_f16(c[nt], ah, bh);
            mma_f16(c[nt], ah, bl);
            mma_f16(c[nt], al, bh);
        }
    }

    // ---- top-2 over this block's 40 candidates (one warp owns each row) ----
    const int qr = lane >> 2, qc = (lane & 3)*2;
    const int vbase = nh*40;
    const int r0 = tile*128 + wrp*16 + qr;

    ull b1[2], b2[2];
    b1[0] = b1[1] = b2[0] = b2[1] = 0xFFFFFFFFFFFFFFFFULL;
    float zs0 = g_zsq[(size_t)r0*2 + g];
    float zs1 = g_zsq[(size_t)(r0 + 8)*2 + g];
    #pragma unroll
    for (int nt = 0; nt < 5; nt++){
        int v0 = vbase + nt*8 + qc;
        float e0 = g_esq[g*V_ + v0];
        float e1 = g_esq[g*V_ + v0 + 1];
        float4 cv = c[nt];
        float d00 = (zs0 - 2.0f*(cv.x*INVS)) + e0;
        float d01 = (zs0 - 2.0f*(cv.y*INVS)) + e1;
        float d10 = (zs1 - 2.0f*(cv.z*INVS)) + e0;
        float d11 = (zs1 - 2.0f*(cv.w*INVS)) + e1;
        upd2(b1[0], b2[0], ((ull)__float_as_uint(d00) << 32) | (unsigned)v0);
        upd2(b1[0], b2[0], ((ull)__float_as_uint(d01) << 32) | (unsigned)(v0+1));
        upd2(b1[1], b2[1], ((ull)__float_as_uint(d10) << 32) | (unsigned)v0);
        upd2(b1[1], b2[1], ((ull)__float_as_uint(d11) << 32) | (unsigned)(v0+1));
    }
    #pragma unroll
    for (int rr = 0; rr < 2; rr++){
        ull x1 = b1[rr], x2 = b2[rr];
        #pragma unroll
        for (int off = 1; off < 4; off <<= 1){
            ull o1 = __shfl_xor_sync(0xffffffffu, x1, off);
            ull o2 = __shfl_xor_sync(0xffffffffu, x2, off);
            ull n2 = umin2(umax2(x1, o1), umin2(x2, o2));
            x1 = umin2(x1, o1);
            x2 = n2;
        }
        if ((lane & 3) == 0){
            int pair = (r0 + rr*8)*2 + g;
            g_top2[(size_t)pair*8 + nh] = make_ulonglong2(x1, x2);
        }
    }
}

// ---------------- K4b: select idx + flag near-ties ---------------------------
__global__ __launch_bounds__(256) void k_sel(){
    int i = blockIdx.x * 256 + threadIdx.x;
    if (i >= NPAIR) return;
    ull b1 = 0xFFFFFFFFFFFFFFFFULL, b2 = 0xFFFFFFFFFFFFFFFFULL;
    #pragma unroll
    for (int j = 0; j < 8; j++){
        ulonglong2 p = g_top2[(size_t)i*8 + j];
        upd2(b1, b2, p.x);
        upd2(b1, b2, p.y);
    }
    g_idx[i] = (int)(unsigned)(b1 & 0xFFFFFFFFULL);
    float m1 = __uint_as_float((unsigned)(b1 >> 32));
    float m2 = __uint_as_float((unsigned)(b2 >> 32));
    if (m2 - m1 < THRESH){
        int p = atomicAdd(&g_wlc, 1);
        g_wl[p] = i;
    }
}

// ---------------- K4c: exact rescue (recompute ze from y) --------------------
__global__ __launch_bounds__(320) void k_rescue(const float* __restrict__ emb,
                                                const float* __restrict__ gn_w,
                                                const float* __restrict__ gn_b){
    __shared__ float sze[256];
    __shared__ ull red[10];
    int tid = threadIdx.x;
    int wid = tid >> 5, lane = tid & 31;

    for (int e = blockIdx.x; e < g_wlc; e += gridDim.x){
        __syncthreads();
        int i = g_wl[e];
        int tok = i >> 1, g = i & 1;
        if (tid < 256){
            int b = tok >> 11;
            float mu = g_mu[b*2 + g], rstd = g_rstd[b*2 + g];
            float yv = g_y[(size_t)tok*C_ + g*D_ + tid];
            sze[tid] = fmaf((yv - mu)*rstd, gn_w[g*D_ + tid], gn_b[g*D_ + tid]);
        }
        __syncthreads();

        const float* ev = emb + (size_t)tid*C_ + g*D_;
        float acc = 0.f;
        #pragma unroll 8
        for (int k = 0; k < D_; k++) acc = fmaf(sze[k], ev[k], acc);
        float d2 = (g_zsq[i] - 2.0f*acc) + g_esq[g*V_ + tid];
        ull best = ((ull)__float_as_uint(d2) << 32) | (unsigned)tid;

        #pragma unroll
        for (int off = 16; off > 0; off >>= 1){
            ull o = __shfl_xor_sync(0xffffffffu, best, off);
            best = umin2(best, o);
        }
        if (lane == 0) red[wid] = best;
        __syncthreads();
        if (tid == 0){
            ull b = red[0];
            #pragma unroll
            for (int wv = 1; wv < 10; wv++) b = umin2(b, red[wv]);
            g_idx[i] = (int)(unsigned)(b & 0xFFFFFFFFULL);
        }
    }
}

// ---------------- K5: gather zq, x_out (ze recomputed), losses, histogram ----
__global__ __launch_bounds__(256) void k_epi(const float* __restrict__ emb,
                                             const float* __restrict__ gn_w,
                                             const float* __restrict__ gn_b,
                                             float* __restrict__ out){
    __shared__ float warp_s[8];
    int tid  = threadIdx.x;
    int wg   = (blockIdx.x * 256 + tid) >> 5;
    int lane = tid & 31, wl = tid >> 5;
    int n = wg >> 1, g = wg & 1;
    int b = n >> 11;
    float mu = g_mu[b*2 + g], rstd = g_rstd[b*2 + g];
    int v = g_idx[wg];

    size_t yb = (size_t)n*C_ + g*D_ + lane*8;
    size_t eb = (size_t)v*C_ + g*D_ + lane*8;
    float y[8], e[8], wv[8], bv[8], r[8];
    ld8(g_y + yb, y);
    ld8(emb + eb, e);
    ld8(gn_w + g*D_ + lane*8, wv);
    ld8(gn_b + g*D_ + lane*8, bv);
    float s = 0.f;
    #pragma unroll
    for (int i = 0; i < 8; i++){
        float z = fmaf((y[i] - mu)*rstd, wv[i], bv[i]);
        float dd = e[i] - z;
        s = fmaf(dd, dd, s);
        r[i] = (e[i] + z) - z;
    }
    *(float4*)(out + yb)     = make_float4(r[0], r[1], r[2], r[3]);
    *(float4*)(out + yb + 4) = make_float4(r[4], r[5], r[6], r[7]);
    #pragma unroll
    for (int off = 16; off > 0; off >>= 1) s += __shfl_xor_sync(0xffffffffu, s, off);
    if (lane == 0){
        warp_s[wl] = s;
        atomicAdd(&g_hist[g*V_ + v], 1);
        out[(size_t)N_TOK*C_ + wg] = (float)v;
    }
    __syncthreads();
    if (tid == 0){
        double a = 0.0;
        #pragma unroll
        for (int i = 0; i < 8; i++) a += (double)warp_s[i];
        g_lpart[blockIdx.x] = a;
    }
}

// ---------------- K6: final scalars ------------------------------------------
__global__ void k_final(float* __restrict__ out){
    __shared__ double sh[512];
    int t = threadIdx.x;
    double a = 0.0;
    for (int j = t*16; j < t*16 + 16; j++) a += g_lpart[j];
    sh[t] = a; __syncthreads();
    for (int off = 256; off > 0; off >>= 1){
        if (t < off) sh[t] += sh[t+off];
        __syncthreads();
    }
    double S = sh[0];
    __syncthreads();

    double h0 = 0.0, h1 = 0.0;
    if (t < V_){
        double p0 = (double)g_hist[t]      / (double)N_TOK;
        double p1 = (double)g_hist[V_ + t] / (double)N_TOK;
        h0 = p0 * log(p0 + 1e-7);
        h1 = p1 * log(p1 + 1e-7);
    }
    sh[t] = h0; __syncthreads();
    for (int off = 256; off > 0; off >>= 1){
        if (t < off) sh[t] += sh[t+off];
        __syncthreads();
    }
    double H0 = sh[0];
    __syncthreads();
    sh[t] = h1; __syncthreads();
    for (int off = 256; off > 0; off >>= 1){
        if (t < off) sh[t] += sh[t+off];
        __syncthreads();
    }
    double H1 = sh[0];

    if (t == 0){
        double ppl = exp(-H0) + exp(-H1);
        double l   = S / (double)((size_t)N_TOK * C_);
        out[(size_t)N_TOK*C_ + NPAIR]     = (float)ppl;
        out[(size_t)N_TOK*C_ + NPAIR + 1] = (float)(l + 0.25*l);
    }
}

// ---------------- launcher ---------------------------------------------------
extern "C" void kernel_launch(void* const* d_in, const int* in_sizes, int n_in,
                              void* d_out, int out_size){
    const float* x   = (const float*)d_in[0];
    const float* cw  = (const float*)d_in[1];
    const float* gw  = (const float*)d_in[2];
    const float* gb  = (const float*)d_in[3];
    const float* emb = (const float*)d_in[4];
    float* out = (float*)d_out;

    k_setup<<<67, 256>>>(cw, emb);               // 1
    k_pack_x<<<dim3(256, 2), 256>>>(x);          // 2
    k_nop<<<1, 32>>>();                          // 3
    k_gemm1<<<dim3(256, 4, 2), 256>>>();         // 4 <- ncu capture slot
    k_stats<<<1, 32>>>();
    k_norm<<<dim3(256, 2), 256>>>(gw, gb);
    k_vq<<<dim3(256, 8, 2), 256>>>();
    k_sel<<<NPAIR/256, 256>>>();
    k_rescue<<<132, 320>>>(emb, gw, gb);
    k_epi<<<8192, 256>>>(emb, gw, gb, out);
    k_final<<<1, 512>>>(out);
}

// round 17
// speedup vs baseline: 1.0423x; 1.0423x over previous
#include <cuda_runtime.h>
#include <cuda_fp16.h>
#include <math.h>
#include <stdint.h>

#define B_     16
#define T_     2048
#define C_     512
#define G_     2
#define D_     256
#define V_     320
#define N_TOK  (B_*T_)           // 32768
#define NPAIR  (N_TOK*G_)        // 65536
#define GN_N   ((double)(T_*D_)) // 524288
#define THRESH 2.5e-4f
#define SCAL   256.0f
#define INVS   (1.0f/256.0f)

typedef unsigned long long ull;

// ---------------- scratch ----------------------------------------------------
__device__ float      g_y  [N_TOK*C_];
__device__ float      g_zsq[NPAIR];
__device__ ulonglong2 g_top2[NPAIR*4];
__device__ int        g_idx[NPAIR];
__device__ int        g_wl [NPAIR];
__device__ int        g_wlc;
__device__ double     g_p1s[32][32];
__device__ double     g_p1q[32][32];
__device__ float      g_mu  [32];
__device__ float      g_rstd[32];
__device__ float      g_esq [G_*V_];
__device__ int        g_hist[G_*V_];
__device__ double     g_lpart[8192];

// fragment-packed operands (half2 planes, hi and lo)
__device__ uint32_t g_xh[2*256*16384];
__device__ uint32_t g_xl[2*256*16384];
__device__ uint32_t g_zh[2*256*16384];
__device__ uint32_t g_zl[2*256*16384];
__device__ uint32_t g_wh[2*32768];       // w   [g][kc][nt(32)][lane][reg]
__device__ uint32_t g_wl_[2*32768];
__device__ uint32_t g_eh[2*40960];       // emb [g][kc][nt(40)][lane][reg]
__device__ uint32_t g_el[2*40960];

// ---------------- helpers ----------------------------------------------------
__device__ __forceinline__ void mma_f16(float4& c, const uint4& a, const uint2& b){
    asm("mma.sync.aligned.m16n8k16.row.col.f32.f16.f16.f32 "
        "{%0,%1,%2,%3}, {%4,%5,%6,%7}, {%8,%9}, {%0,%1,%2,%3};"
        : "+f"(c.x), "+f"(c.y), "+f"(c.z), "+f"(c.w)
        : "r"(a.x), "r"(a.y), "r"(a.z), "r"(a.w), "r"(b.x), "r"(b.y));
}
__device__ __forceinline__ uint32_t hsplit(float v0, float v1, uint32_t& lo){
    __half h0 = __float2half_rn(v0), h1 = __float2half_rn(v1);
    __half l0 = __float2half_rn(v0 - __half2float(h0));
    __half l1 = __float2half_rn(v1 - __half2float(h1));
    __half2 H = __halves2half2(h0, h1), L = __halves2half2(l0, l1);
    lo = *reinterpret_cast<uint32_t*>(&L);
    return *reinterpret_cast<uint32_t*>(&H);
}
__device__ __forceinline__ void sts_A16(uint32_t* hi, uint32_t* lo,
                                        int row, int k, float v0, float v1){
    int kp = k >> 1, mt = row >> 4, r = row & 15;
    int reg = ((r >> 3) & 1) | (((kp >> 2) & 1) << 1);
    int idx = mt*128 + ((r & 7)*4 + (kp & 3))*4 + reg;
    uint32_t L, H = hsplit(v0, v1, L);
    hi[idx] = H; lo[idx] = L;
}
template<int NT>
__device__ __forceinline__ void sts_B16(uint32_t* hi, uint32_t* lo,
                                        int n, int k, float v0, float v1){
    int kp = k >> 1, nt = n >> 3;
    int reg = (kp >> 2) & 1;
    int idx = nt*64 + ((n & 7)*4 + (kp & 3))*2 + reg;
    uint32_t L, H = hsplit(v0, v1, L);
    hi[idx] = H; lo[idx] = L;
}
__device__ __forceinline__ void ld8(const float* __restrict__ p, float* r){
    float4 a = *(const float4*)p;
    float4 b = *(const float4*)(p + 4);
    r[0]=a.x; r[1]=a.y; r[2]=a.z; r[3]=a.w;
    r[4]=b.x; r[5]=b.y; r[6]=b.z; r[7]=b.w;
}
__device__ __forceinline__ ull umin2(ull a, ull b){ return a < b ? a : b; }
__device__ __forceinline__ ull umax2(ull a, ull b){ return a > b ? a : b; }
__device__ __forceinline__ void upd2(ull& b1, ull& b2, ull p){
    if (p < b1){ b2 = b1; b1 = p; }
    else if (p < b2){ b2 = p; }
}
__device__ __forceinline__ void cp16(uint32_t d, const void* s){
    asm volatile("cp.async.ca.shared.global [%0], [%1], 16;" :: "r"(d), "l"(s));
}
#define CP_COMMIT() asm volatile("cp.async.commit_group;" ::: "memory")
#define CP_WAIT0()  asm volatile("cp.async.wait_group 0;"  ::: "memory")

// ---------------- K0: setup (pack w, pack emb, init) -------------------------
__global__ __launch_bounds__(256) void k_setup(const float* __restrict__ w,
                                               const float* __restrict__ emb){
    __shared__ uint32_t sh[2560], sl[2560];
    int bid = blockIdx.x, tid = threadIdx.x;
    if (bid < 32){
        int g = bid >> 4, kc = bid & 15;
        const float* Bg = w + (size_t)g*D_*D_;
        #pragma unroll
        for (int it = 0; it < 4; it++){
            int f4 = it*256 + tid, row = f4 >> 2, kq = (f4 & 3)*4;
            float4 v = *(const float4*)(Bg + (size_t)row*D_ + kc*16 + kq);
            sts_B16<32>(sh, sl, row, kq,   v.x*SCAL, v.y*SCAL);
            sts_B16<32>(sh, sl, row, kq+2, v.z*SCAL, v.w*SCAL);
        }
        __syncthreads();
        #pragma unroll
        for (int j = 0; j < 8; j++){
            g_wh [g*32768 + kc*2048 + j*256 + tid] = sh[j*256 + tid];
            g_wl_[g*32768 + kc*2048 + j*256 + tid] = sl[j*256 + tid];
        }
    } else if (bid < 64){
        int g = (bid-32) >> 4, kc = (bid-32) & 15;
        const float* Bg = emb + g*D_;
        #pragma unroll
        for (int it = 0; it < 5; it++){
            int f4 = it*256 + tid, row = f4 >> 2, kq = (f4 & 3)*4;
            float4 v = *(const float4*)(Bg + (size_t)row*C_ + kc*16 + kq);
            sts_B16<40>(sh, sl, row, kq,   v.x*SCAL, v.y*SCAL);
            sts_B16<40>(sh, sl, row, kq+2, v.z*SCAL, v.w*SCAL);
        }
        __syncthreads();
        #pragma unroll
        for (int j = 0; j < 10; j++){
            g_eh[g*40960 + kc*2560 + j*256 + tid] = sh[j*256 + tid];
            g_el[g*40960 + kc*2560 + j*256 + tid] = sl[j*256 + tid];
        }
    } else {
        int i = (bid - 64)*256 + tid;
        if (i == 0) g_wlc = 0;
        if (i < G_*V_){
            g_hist[i] = 0;
            int g = i / V_, v = i % V_;
            const float4* p = (const float4*)(emb + (size_t)v*C_ + g*D_);
            float s = 0.f;
            #pragma unroll 16
            for (int q = 0; q < D_/4; q++){
                float4 e = p[q];
                s += e.x*e.x + e.y*e.y + e.z*e.z + e.w*e.w;
            }
            g_esq[i] = s;
        }
    }
}

// ---------------- K0b: pack x into fragment layout ---------------------------
__global__ __launch_bounds__(256) void k_pack_x(const float* __restrict__ x){
    __shared__ uint32_t sh[1024], sl[1024];
    int tile = blockIdx.x, g = blockIdx.y, tid = threadIdx.x;
    const float* Ag = x + (size_t)tile*128*C_ + g*D_;
    size_t base = ((size_t)(g*256 + tile)) * 16384;
    for (int kc = 0; kc < 16; kc++){
        #pragma unroll
        for (int it = 0; it < 2; it++){
            int f4 = it*256 + tid, row = f4 >> 2, kq = (f4 & 3)*4;
            float4 v = *(const float4*)(Ag + (size_t)row*C_ + kc*16 + kq);
            sts_A16(sh, sl, row, kq,   v.x, v.y);
            sts_A16(sh, sl, row, kq+2, v.z, v.w);
        }
        __syncthreads();
        #pragma unroll
        for (int j = 0; j < 4; j++){
            g_xh[base + kc*1024 + j*256 + tid] = sh[j*256 + tid];
            g_xl[base + kc*1024 + j*256 + tid] = sl[j*256 + tid];
        }
        __syncthreads();
    }
}

// ---------------- K1: GEMM1 — A reg-prefetch, B cp.async smem ring -----------
// grid (256, 2, 2) = (tile, bn, g)
__global__ __launch_bounds__(256, 2) void k_gemm1(){
    __shared__ uint32_t sB[2][2048];
    __shared__ double rs[256], rq[256];
    const int tile = blockIdx.x, bn = blockIdx.y, g = blockIdx.z;
    const int tid  = threadIdx.x;
    const int lane = tid & 31, wrp = tid >> 5;
    const int warpm = wrp & 3, warpn = wrp >> 2;

    const uint32_t* Ah = g_xh + ((size_t)(g*256 + tile))*16384;
    const uint32_t* Al = g_xl + ((size_t)(g*256 + tile))*16384;
    const uint32_t* Bh = g_wh  + g*32768 + bn*1024;
    const uint32_t* Bl = g_wl_ + g*32768 + bn*1024;

    float4 c[2][8];
    #pragma unroll
    for (int i = 0; i < 2; i++)
        #pragma unroll
        for (int j = 0; j < 8; j++) c[i][j] = make_float4(0.f,0.f,0.f,0.f);

    cp16((uint32_t)__cvta_generic_to_shared(&sB[0][tid*4]),        Bh + tid*4);
    cp16((uint32_t)__cvta_generic_to_shared(&sB[0][1024 + tid*4]), Bl + tid*4);
    CP_COMMIT();

    int aoff = warpm*256 + lane*4;
    uint4 nah0 = *(const uint4*)(Ah + aoff);
    uint4 nah1 = *(const uint4*)(Ah + aoff + 128);
    uint4 nal0 = *(const uint4*)(Al + aoff);
    uint4 nal1 = *(const uint4*)(Al + aoff + 128);

    for (int kc = 0; kc < 16; kc++){
        CP_WAIT0();
        __syncthreads();
        if (kc < 15){
            cp16((uint32_t)__cvta_generic_to_shared(&sB[(kc+1)&1][tid*4]),
                 Bh + (kc+1)*2048 + tid*4);
            cp16((uint32_t)__cvta_generic_to_shared(&sB[(kc+1)&1][1024 + tid*4]),
                 Bl + (kc+1)*2048 + tid*4);
            CP_COMMIT();
        }

        uint4 ah0 = nah0, ah1 = nah1, al0 = nal0, al1 = nal1;
        if (kc < 15){
            int ao = (kc+1)*1024 + aoff;
            nah0 = *(const uint4*)(Ah + ao);
            nah1 = *(const uint4*)(Ah + ao + 128);
            nal0 = *(const uint4*)(Al + ao);
            nal1 = *(const uint4*)(Al + ao + 128);
        }
        const uint32_t* sb = sB[kc & 1];
        int nb = warpn*8*64 + lane*2;
        uint2 bh = *(const uint2*)(sb + nb);
        uint2 bl = *(const uint2*)(sb + 1024 + nb);
        #pragma unroll
        for (int nt = 0; nt < 8; nt++){
            uint2 nbh, nbl;
            if (nt < 7){
                nbh = *(const uint2*)(sb + nb + (nt+1)*64);
                nbl = *(const uint2*)(sb + 1024 + nb + (nt+1)*64);
            }
            mma_f16(c[0][nt], ah0, bh);
            mma_f16(c[1][nt], ah1, bh);
            mma_f16(c[0][nt], ah0, bl);
            mma_f16(c[1][nt], ah1, bl);
            mma_f16(c[0][nt], al0, bh);
            mma_f16(c[1][nt], al1, bh);
            bh = nbh; bl = nbl;
        }
    }

    const int qr = lane >> 2, qc = (lane & 3)*2;
    double s = 0.0, q = 0.0;
    const int rowbase = tile*128 + warpm*32;
    const int colbase = g*D_ + bn*128 + warpn*64;
    #pragma unroll
    for (int mt = 0; mt < 2; mt++){
        #pragma unroll
        for (int nt = 0; nt < 8; nt++){
            float4 v = make_float4(c[mt][nt].x*INVS, c[mt][nt].y*INVS,
                                   c[mt][nt].z*INVS, c[mt][nt].w*INVS);
            int r0 = rowbase + mt*16 + qr;
            int col = colbase + nt*8 + qc;
            *(float2*)(g_y + (size_t)r0*C_ + col)     = make_float2(v.x, v.y);
            *(float2*)(g_y + (size_t)(r0+8)*C_ + col) = make_float2(v.z, v.w);
            s += (double)v.x + (double)v.y + (double)v.z + (double)v.w;
            q += (double)v.x*v.x + (double)v.y*v.y + (double)v.z*v.z + (double)v.w*v.w;
        }
    }
    rs[tid] = s; rq[tid] = q;
    __syncthreads();
    for (int off = 128; off > 0; off >>= 1){
        if (tid < off){ rs[tid] += rs[tid+off]; rq[tid] += rq[tid+off]; }
        __syncthreads();
    }
    if (tid == 0){
        int b2g = (tile >> 4)*2 + g;
        g_p1s[b2g][(tile & 15)*2 + bn] = rs[0];
        g_p1q[b2g][(tile & 15)*2 + bn] = rq[0];
    }
}

// ---------------- K3: normalize (inline stats) -> ze frag pack + zsq ---------
__global__ __launch_bounds__(256) void k_norm(const float* __restrict__ gn_w,
                                              const float* __restrict__ gn_b){
    __shared__ uint32_t sh[1024], sl[1024];
    __shared__ float s_mu, s_rstd;
    int tile = blockIdx.x, g = blockIdx.y, tid = threadIdx.x;
    int b = tile >> 4;

    // inline groupnorm stats: identical 32-term sequential double sum
    if (tid == 0){
        int i = b*2 + g;
        double s = 0.0, q = 0.0;
        for (int j = 0; j < 32; j++){ s += g_p1s[i][j]; q += g_p1q[i][j]; }
        double mud  = s / GN_N;
        double var  = q / GN_N - mud*mud;
        float muf   = (float)mud;
        float rstdf = (float)(1.0 / sqrt(var + 1e-5));
        s_mu = muf; s_rstd = rstdf;
        if ((tile & 15) == 0){ g_mu[i] = muf; g_rstd[i] = rstdf; }
    }
    __syncthreads();
    const float mu = s_mu, rstd = s_rstd;
    const float* Yg = g_y + (size_t)tile*128*C_ + g*D_;
    size_t base = ((size_t)(g*256 + tile)) * 16384;

    float zp0 = 0.f, zp1 = 0.f;
    for (int kc = 0; kc < 16; kc++){
        #pragma unroll
        for (int it = 0; it < 2; it++){
            int f4 = it*256 + tid, row = f4 >> 2, kq = (f4 & 3)*4;
            float4 y4 = *(const float4*)(Yg + (size_t)row*C_ + kc*16 + kq);
            float4 wv = *(const float4*)(gn_w + g*D_ + kc*16 + kq);
            float4 bv = *(const float4*)(gn_b + g*D_ + kc*16 + kq);
            float4 z;
            z.x = fmaf((y4.x - mu)*rstd, wv.x, bv.x);
            z.y = fmaf((y4.y - mu)*rstd, wv.y, bv.y);
            z.z = fmaf((y4.z - mu)*rstd, wv.z, bv.z);
            z.w = fmaf((y4.w - mu)*rstd, wv.w, bv.w);
            float p = (it == 0) ? zp0 : zp1;
            p = fmaf(z.x, z.x, p); p = fmaf(z.y, z.y, p);
            p = fmaf(z.z, z.z, p); p = fmaf(z.w, z.w, p);
            if (it == 0) zp0 = p; else zp1 = p;
            sts_A16(sh, sl, row, kq,   z.x, z.y);
            sts_A16(sh, sl, row, kq+2, z.z, z.w);
        }
        __syncthreads();
        #pragma unroll
        for (int j = 0; j < 4; j++){
            g_zh[base + kc*1024 + j*256 + tid] = sh[j*256 + tid];
            g_zl[base + kc*1024 + j*256 + tid] = sl[j*256 + tid];
        }
        __syncthreads();
    }
    float t0 = zp0, t1 = zp1;
    t0 += __shfl_xor_sync(0xffffffffu, t0, 1);
    t0 += __shfl_xor_sync(0xffffffffu, t0, 2);
    t1 += __shfl_xor_sync(0xffffffffu, t1, 1);
    t1 += __shfl_xor_sync(0xffffffffu, t1, 2);
    if ((tid & 3) == 0){
        int r0 = tid >> 2;
        g_zsq[(size_t)(tile*128 + r0)*2 + g]      = t0;
        g_zsq[(size_t)(tile*128 + 64 + r0)*2 + g] = t1;
    }
}

// ---------------- K4: VQ — A reg-prefetch, B cp.async smem ring --------------
// grid (256, 4, 2) = (tile, nh, g)
__global__ __launch_bounds__(256, 2) void k_vq(){
    __shared__ uint32_t sV[2][1280];
    __shared__ ulonglong2 sTop[256];
    const int tile = blockIdx.x, nh = blockIdx.y, g = blockIdx.z;
    const int tid  = threadIdx.x;
    const int lane = tid & 31, wrp = tid >> 5;
    const int warpm = wrp & 3, warpn = wrp >> 2;

    const uint32_t* Ah = g_zh + ((size_t)(g*256 + tile))*16384;
    const uint32_t* Al = g_zl + ((size_t)(g*256 + tile))*16384;
    const uint32_t* Bh = g_eh + g*40960 + nh*640;
    const uint32_t* Bl = g_el + g*40960 + nh*640;

    float4 c[2][5];
    #pragma unroll
    for (int i = 0; i < 2; i++)
        #pragma unroll
        for (int j = 0; j < 5; j++) c[i][j] = make_float4(0.f,0.f,0.f,0.f);

    const int loj = tid - 96;
    if (tid < 160)
        cp16((uint32_t)__cvta_generic_to_shared(&sV[0][tid*4]), Bh + tid*4);
    if (loj >= 0)
        cp16((uint32_t)__cvta_generic_to_shared(&sV[0][640 + loj*4]), Bl + loj*4);
    CP_COMMIT();

    int aoff = warpm*256 + lane*4;
    uint4 nah0 = *(const uint4*)(Ah + aoff);
    uint4 nah1 = *(const uint4*)(Ah + aoff + 128);
    uint4 nal0 = *(const uint4*)(Al + aoff);
    uint4 nal1 = *(const uint4*)(Al + aoff + 128);

    for (int kc = 0; kc < 16; kc++){
        CP_WAIT0();
        __syncthreads();
        if (kc < 15){
            if (tid < 160)
                cp16((uint32_t)__cvta_generic_to_shared(&sV[(kc+1)&1][tid*4]),
                     Bh + (kc+1)*2560 + tid*4);
            if (loj >= 0)
                cp16((uint32_t)__cvta_generic_to_shared(&sV[(kc+1)&1][640 + loj*4]),
                     Bl + (kc+1)*2560 + loj*4);
            CP_COMMIT();
        }

        uint4 ah0 = nah0, ah1 = nah1, al0 = nal0, al1 = nal1;
        if (kc < 15){
            int ao = (kc+1)*1024 + aoff;
            nah0 = *(const uint4*)(Ah + ao);
            nah1 = *(const uint4*)(Ah + ao + 128);
            nal0 = *(const uint4*)(Al + ao);
            nal1 = *(const uint4*)(Al + ao + 128);
        }
        const uint32_t* sb = sV[kc & 1];
        int nb = warpn*5*64 + lane*2;
        uint2 bh = *(const uint2*)(sb + nb);
        uint2 bl = *(const uint2*)(sb + 640 + nb);
        #pragma unroll
        for (int nt = 0; nt < 5; nt++){
            uint2 nbh, nbl;
            if (nt < 4){
                nbh = *(const uint2*)(sb + nb + (nt+1)*64);
                nbl = *(const uint2*)(sb + 640 + nb + (nt+1)*64);
            }
            mma_f16(c[0][nt], ah0, bh);
            mma_f16(c[1][nt], ah1, bh);
            mma_f16(c[0][nt], ah0, bl);
            mma_f16(c[1][nt], ah1, bl);
            mma_f16(c[0][nt], al0, bh);
            mma_f16(c[1][nt], al1, bh);
            bh = nbh; bl = nbl;
        }
    }

    // ---- top-2 over this block's 80 candidates ----
    const int qr = lane >> 2, qc = (lane & 3)*2;
    const int vbase = nh*80 + warpn*40;
    const int rowbase = tile*128 + warpm*32;

    ull b1[2][2], b2[2][2];
    #pragma unroll
    for (int mt = 0; mt < 2; mt++)
        #pragma unroll
        for (int rr = 0; rr < 2; rr++){
            b1[mt][rr] = 0xFFFFFFFFFFFFFFFFULL;
            b2[mt][rr] = 0xFFFFFFFFFFFFFFFFULL;
        }
    float zs[2][2];
    #pragma unroll
    for (int mt = 0; mt < 2; mt++){
        int r0 = rowbase + mt*16 + qr;
        zs[mt][0] = g_zsq[(size_t)r0*2 + g];
        zs[mt][1] = g_zsq[(size_t)(r0 + 8)*2 + g];
    }
    #pragma unroll
    for (int nt = 0; nt < 5; nt++){
        int v0 = vbase + nt*8 + qc;
        float e0 = g_esq[g*V_ + v0];
        float e1 = g_esq[g*V_ + v0 + 1];
        #pragma unroll
        for (int mt = 0; mt < 2; mt++){
            float4 cv = c[mt][nt];
            float d00 = (zs[mt][0] - 2.0f*(cv.x*INVS)) + e0;
            float d01 = (zs[mt][0] - 2.0f*(cv.y*INVS)) + e1;
            float d10 = (zs[mt][1] - 2.0f*(cv.z*INVS)) + e0;
            float d11 = (zs[mt][1] - 2.0f*(cv.w*INVS)) + e1;
            upd2(b1[mt][0], b2[mt][0], ((ull)__float_as_uint(d00) << 32) | (unsigned)v0);
            upd2(b1[mt][0], b2[mt][0], ((ull)__float_as_uint(d01) << 32) | (unsigned)(v0+1));
            upd2(b1[mt][1], b2[mt][1], ((ull)__float_as_uint(d10) << 32) | (unsigned)v0);
            upd2(b1[mt][1], b2[mt][1], ((ull)__float_as_uint(d11) << 32) | (unsigned)(v0+1));
        }
    }
    #pragma unroll
    for (int mt = 0; mt < 2; mt++){
        #pragma unroll
        for (int rr = 0; rr < 2; rr++){
            ull x1 = b1[mt][rr], x2 = b2[mt][rr];
            #pragma unroll
            for (int off = 1; off < 4; off <<= 1){
                ull o1 = __shfl_xor_sync(0xffffffffu, x1, off);
                ull o2 = __shfl_xor_sync(0xffffffffu, x2, off);
                ull n2 = umin2(umax2(x1, o1), umin2(x2, o2));
                x1 = umin2(x1, o1);
                x2 = n2;
            }
            if ((lane & 3) == 0){
                int lr = warpm*32 + mt*16 + rr*8 + qr;
                sTop[lr*2 + warpn] = make_ulonglong2(x1, x2);
            }
        }
    }
    __syncthreads();
    if (tid < 128){
        ulonglong2 p0 = sTop[tid*2 + 0];
        ulonglong2 p1 = sTop[tid*2 + 1];
        ull gb1 = umin2(p0.x, p1.x);
        ull gb2 = umin2(umax2(p0.x, p1.x), umin2(p0.y, p1.y));
        int pair = (tile*128 + tid)*2 + g;
        g_top2[pair*4 + nh] = make_ulonglong2(gb1, gb2);
    }
}

// ---------------- K4b: select idx + flag near-ties ---------------------------
__global__ __launch_bounds__(256) void k_sel(){
    int i = blockIdx.x * 256 + threadIdx.x;
    if (i >= NPAIR) return;
    ull b1 = 0xFFFFFFFFFFFFFFFFULL, b2 = 0xFFFFFFFFFFFFFFFFULL;
    #pragma unroll
    for (int j = 0; j < 4; j++){
        ulonglong2 p = g_top2[i*4 + j];
        upd2(b1, b2, p.x);
        upd2(b1, b2, p.y);
    }
    g_idx[i] = (int)(unsigned)(b1 & 0xFFFFFFFFULL);
    float m1 = __uint_as_float((unsigned)(b1 >> 32));
    float m2 = __uint_as_float((unsigned)(b2 >> 32));
    if (m2 - m1 < THRESH){
        int p = atomicAdd(&g_wlc, 1);
        g_wl[p] = i;
    }
}

// ---------------- K4c: exact rescue (recompute ze from y) --------------------
__global__ __launch_bounds__(320) void k_rescue(const float* __restrict__ emb,
                                                const float* __restrict__ gn_w,
                                                const float* __restrict__ gn_b){
    __shared__ float sze[256];
    __shared__ ull red[10];
    int tid = threadIdx.x;
    int wid = tid >> 5, lane = tid & 31;

    for (int e = blockIdx.x; e < g_wlc; e += gridDim.x){
        __syncthreads();
        int i = g_wl[e];
        int tok = i >> 1, g = i & 1;
        if (tid < 256){
            int b = tok >> 11;
            float mu = g_mu[b*2 + g], rstd = g_rstd[b*2 + g];
            float yv = g_y[(size_t)tok*C_ + g*D_ + tid];
            sze[tid] = fmaf((yv - mu)*rstd, gn_w[g*D_ + tid], gn_b[g*D_ + tid]);
        }
        __syncthreads();

        const float* ev = emb + (size_t)tid*C_ + g*D_;
        float acc = 0.f;
        #pragma unroll 8
        for (int k = 0; k < D_; k++) acc = fmaf(sze[k], ev[k], acc);
        float d2 = (g_zsq[i] - 2.0f*acc) + g_esq[g*V_ + tid];
        ull best = ((ull)__float_as_uint(d2) << 32) | (unsigned)tid;

        #pragma unroll
        for (int off = 16; off > 0; off >>= 1){
            ull o = __shfl_xor_sync(0xffffffffu, best, off);
            best = umin2(best, o);
        }
        if (lane == 0) red[wid] = best;
        __syncthreads();
        if (tid == 0){
            ull b = red[0];
            #pragma unroll
            for (int wv = 1; wv < 10; wv++) b = umin2(b, red[wv]);
            g_idx[i] = (int)(unsigned)(b & 0xFFFFFFFFULL);
        }
    }
}

// ---------------- K5: gather zq, x_out (ze recomputed), losses, histogram ----
__global__ __launch_bounds__(256) void k_epi(const float* __restrict__ emb,
                                             const float* __restrict__ gn_w,
                                             const float* __restrict__ gn_b,
                                             float* __restrict__ out){
    __shared__ float warp_s[8];
    int tid  = threadIdx.x;
    int wg   = (blockIdx.x * 256 + tid) >> 5;
    int lane = tid & 31, wl = tid >> 5;
    int n = wg >> 1, g = wg & 1;
    int b = n >> 11;
    float mu = g_mu[b*2 + g], rstd = g_rstd[b*2 + g];
    int v = g_idx[wg];

    size_t yb = (size_t)n*C_ + g*D_ + lane*8;
    size_t eb = (size_t)v*C_ + g*D_ + lane*8;
    float y[8], e[8], wv[8], bv[8], r[8];
    ld8(g_y + yb, y);
    ld8(emb + eb, e);
    ld8(gn_w + g*D_ + lane*8, wv);
    ld8(gn_b + g*D_ + lane*8, bv);
    float s = 0.f;
    #pragma unroll
    for (int i = 0; i < 8; i++){
        float z = fmaf((y[i] - mu)*rstd, wv[i], bv[i]);
        float dd = e[i] - z;
        s = fmaf(dd, dd, s);
        r[i] = (e[i] + z) - z;
    }
    *(float4*)(out + yb)     = make_float4(r[0], r[1], r[2], r[3]);
    *(float4*)(out + yb + 4) = make_float4(r[4], r[5], r[6], r[7]);
    #pragma unroll
    for (int off = 16; off > 0; off >>= 1) s += __shfl_xor_sync(0xffffffffu, s, off);
    if (lane == 0){
        warp_s[wl] = s;
        atomicAdd(&g_hist[g*V_ + v], 1);
        out[(size_t)N_TOK*C_ + wg] = (float)v;
    }
    __syncthreads();
    if (tid == 0){
        double a = 0.0;
        #pragma unroll
        for (int i = 0; i < 8; i++) a += (double)warp_s[i];
        g_lpart[blockIdx.x] = a;
    }
}

// ---------------- K6: final scalars ------------------------------------------
__global__ void k_final(float* __restrict__ out){
    __shared__ double sh[512];
    int t = threadIdx.x;
    double a = 0.0;
    for (int j = t*16; j < t*16 + 16; j++) a += g_lpart[j];
    sh[t] = a; __syncthreads();
    for (int off = 256; off > 0; off >>= 1){
        if (t < off) sh[t] += sh[t+off];
        __syncthreads();
    }
    double S = sh[0];
    __syncthreads();

    double h0 = 0.0, h1 = 0.0;
    if (t < V_){
        double p0 = (double)g_hist[t]      / (double)N_TOK;
        double p1 = (double)g_hist[V_ + t] / (double)N_TOK;
        h0 = p0 * log(p0 + 1e-7);
        h1 = p1 * log(p1 + 1e-7);
    }
    sh[t] = h0; __syncthreads();
    for (int off = 256; off > 0; off >>= 1){
        if (t < off) sh[t] += sh[t+off];
        __syncthreads();
    }
    double H0 = sh[0];
    __syncthreads();
    sh[t] = h1; __syncthreads();
    for (int off = 256; off > 0; off >>= 1){
        if (t < off) sh[t] += sh[t+off];
        __syncthreads();
    }
    double H1 = sh[0];

    if (t == 0){
        double ppl = exp(-H0) + exp(-H1);
        double l   = S / (double)((size_t)N_TOK * C_);
        out[(size_t)N_TOK*C_ + NPAIR]     = (float)ppl;
        out[(size_t)N_TOK*C_ + NPAIR + 1] = (float)(l + 0.25*l);
    }
}

// ---------------- launcher ---------------------------------------------------
extern "C" void kernel_launch(void* const* d_in, const int* in_sizes, int n_in,
                              void* d_out, int out_size){
    const float* x   = (const float*)d_in[0];
    const float* cw  = (const float*)d_in[1];
    const float* gw  = (const float*)d_in[2];
    const float* gb  = (const float*)d_in[3];
    const float* emb = (const float*)d_in[4];
    float* out = (float*)d_out;

    k_setup<<<67, 256>>>(cw, emb);               // 1
    k_pack_x<<<dim3(256, 2), 256>>>(x);          // 2
    k_gemm1<<<dim3(256, 2, 2), 256>>>();         // 3
    k_norm<<<dim3(256, 2), 256>>>(gw, gb);       // 4 <- ncu capture slot
    k_vq<<<dim3(256, 4, 2), 256>>>();            // 5
    k_sel<<<NPAIR/256, 256>>>();                 // 6
    k_rescue<<<132, 320>>>(emb, gw, gb);         // 7
    k_epi<<<8192, 256>>>(emb, gw, gb, out);      // 8
    k_final<<<1, 512>>>(out);                    // 9
}